// round 5
// baseline (speedup 1.0000x reference)
#include <cuda_runtime.h>
#include <math.h>

#define Wn 2048
#define Cn 24
#define Vn 101
#define En 512
#define H1 1024
#define H2 1024
#define G1 3072
#define G2 3072
#define NCTA2 128
#define STEPS 2048

// ---- scratch (__device__ globals; no allocations allowed) ----
__device__ float g_table[Vn * G1];    // gi lookup per vocab id
__device__ float g_h1[Wn * H1];       // layer-1 hidden state -> word_emb
__device__ float g_gh[Wn * G1];       // layer-1 recurrent gates
__device__ float g_gif[Wn * G2];      // layer-2 fwd input gates
__device__ float g_gib[Wn * G2];      // layer-2 bwd input gates
__device__ float g_h2[2][2][H2];      // [dir][parity][dim]
__device__ unsigned g_bar;

__global__ void init_kernel() {
    int i = blockIdx.x * 256 + threadIdx.x;
    if (i < Wn * H1) g_h1[i] = 0.f;
    if (i < 4 * H2) ((float*)g_h2)[i] = 0.f;
    if (i == 0) g_bar = 0u;
}

// ---- packed f32x2 helpers (FFMA2 only reachable via PTX) ----
__device__ __forceinline__ unsigned long long pk2(float lo, float hi) {
    unsigned long long r;
    asm("mov.b64 %0,{%1,%2};" : "=l"(r) : "f"(lo), "f"(hi));
    return r;
}
__device__ __forceinline__ void upk2(unsigned long long v, float& lo, float& hi) {
    asm("mov.b64 {%0,%1},%2;" : "=f"(lo), "=f"(hi) : "l"(v));
}
__device__ __forceinline__ void fma2(unsigned long long& c, unsigned long long a, unsigned long long b) {
    asm("fma.rn.f32x2 %0,%1,%2,%0;" : "+l"(c) : "l"(a), "l"(b));
}

// ---- fp32 SGEMM (NT): C[m][n] = sum_k A[m][k]*B[n][k] + bias[n] ----
// M%128==0, N%128==0, K%16==0. 256 threads, 128x128 tile, 8x8 microtile.
__global__ void __launch_bounds__(256, 2) sgemm_nt(const float* __restrict__ A,
                                                   const float* __restrict__ B,
                                                   float* __restrict__ C,
                                                   const float* __restrict__ bias,
                                                   int M, int N, int K) {
    __shared__ __align__(16) float As[16][132];
    __shared__ __align__(16) float Bs[16][132];
    const int bm = blockIdx.y * 128, bn = blockIdx.x * 128;
    const int tid = threadIdx.x;
    const int tx = tid & 15, ty = tid >> 4;
    const int lr = tid >> 2, lk = (tid & 3) << 2;

    unsigned long long acc[8][4];
#pragma unroll
    for (int i = 0; i < 8; i++)
#pragma unroll
        for (int j = 0; j < 4; j++) acc[i][j] = 0ull;

    for (int k0 = 0; k0 < K; k0 += 16) {
#pragma unroll
        for (int hh = 0; hh < 2; hh++) {
            int r = lr + hh * 64;
            float4 va = *(const float4*)(A + (size_t)(bm + r) * K + k0 + lk);
            As[lk + 0][r] = va.x; As[lk + 1][r] = va.y;
            As[lk + 2][r] = va.z; As[lk + 3][r] = va.w;
            float4 vb = *(const float4*)(B + (size_t)(bn + r) * K + k0 + lk);
            Bs[lk + 0][r] = vb.x; Bs[lk + 1][r] = vb.y;
            Bs[lk + 2][r] = vb.z; Bs[lk + 3][r] = vb.w;
        }
        __syncthreads();
#pragma unroll
        for (int kk = 0; kk < 16; kk++) {
            float4 a0 = *(const float4*)&As[kk][ty * 4];
            float4 a1 = *(const float4*)&As[kk][64 + ty * 4];
            float4 b0 = *(const float4*)&Bs[kk][tx * 4];
            float4 b1 = *(const float4*)&Bs[kk][64 + tx * 4];
            unsigned long long bp0 = pk2(b0.x, b0.y), bp1 = pk2(b0.z, b0.w);
            unsigned long long bp2 = pk2(b1.x, b1.y), bp3 = pk2(b1.z, b1.w);
            float av[8] = {a0.x, a0.y, a0.z, a0.w, a1.x, a1.y, a1.z, a1.w};
#pragma unroll
            for (int i = 0; i < 8; i++) {
                unsigned long long ap = pk2(av[i], av[i]);
                fma2(acc[i][0], ap, bp0); fma2(acc[i][1], ap, bp1);
                fma2(acc[i][2], ap, bp2); fma2(acc[i][3], ap, bp3);
            }
        }
        __syncthreads();
    }

#pragma unroll
    for (int i = 0; i < 8; i++) {
        int m = bm + ((i < 4) ? (ty * 4 + i) : (64 + ty * 4 + i - 4));
        float o[8];
        upk2(acc[i][0], o[0], o[1]); upk2(acc[i][1], o[2], o[3]);
        upk2(acc[i][2], o[4], o[5]); upk2(acc[i][3], o[6], o[7]);
        int n0 = bn + tx * 4, n1 = bn + 64 + tx * 4;
#pragma unroll
        for (int j = 0; j < 4; j++) { o[j] += bias[n0 + j]; o[4 + j] += bias[n1 + j]; }
        *(float4*)(C + (size_t)m * N + n0) = make_float4(o[0], o[1], o[2], o[3]);
        *(float4*)(C + (size_t)m * N + n1) = make_float4(o[4], o[5], o[6], o[7]);
    }
}

// ---- gi lookup: g_table[v][n] = dot(emb[v], Wih1[n]) + bih1[n] ----
__global__ void table_kernel(const float* __restrict__ emb,
                             const float* __restrict__ Wih1,
                             const float* __restrict__ bih1) {
    __shared__ __align__(16) float e[En];
    int v = blockIdx.y;
    int tid = threadIdx.x, warp = tid >> 5, lane = tid & 31;
    for (int i = tid; i < En; i += 256) e[i] = emb[v * En + i];
    __syncthreads();
    int rbase = blockIdx.x * 64 + warp * 8;
    for (int rr = 0; rr < 8; rr++) {
        int row = rbase + rr;
        const float4* wp = (const float4*)(Wih1 + (size_t)row * En);
        const float4* ep = (const float4*)e;
        float s = 0.f;
#pragma unroll
        for (int k = 0; k < 4; k++) {
            float4 wv = wp[lane + 32 * k];
            float4 ev = ep[lane + 32 * k];
            s += wv.x * ev.x + wv.y * ev.y + wv.z * ev.z + wv.w * ev.w;
        }
        for (int off = 16; off; off >>= 1) s += __shfl_xor_sync(0xffffffffu, s, off);
        if (lane == 0) g_table[v * G1 + row] = s + bih1[row];
    }
}

// ---- layer-1 GRU pointwise ----
__global__ void gru1_kernel(const int* __restrict__ x, float* __restrict__ out, int t) {
    int idx = blockIdx.x * 256 + threadIdx.x;   // 0 .. Wn*H1
    int w = idx >> 10, j = idx & 1023;
    int ch = x[w * Cn + t];
    const float* tb = g_table + ch * G1;
    const float* gh = g_gh + (size_t)w * G1;
    float r = 1.f / (1.f + expf(-(tb[j] + gh[j])));
    float z = 1.f / (1.f + expf(-(tb[H1 + j] + gh[H1 + j])));
    float n = tanhf(tb[2 * H1 + j] + r * gh[2 * H1 + j]);
    float hp = g_h1[idx];
    float hn = (1.f - z) * n + z * hp;
    g_h1[idx] = hn;
    if (t == Cn - 1) out[idx] = hn;   // word_emb -> d_out
}

// ---- layer-2 persistent bidirectional GRU (batch 1, 2048 steps) ----
// 128 CTAs: dir = cta>>6, each owns 16 h-dims (48 gate rows) with weights in SMEM.
__global__ void __launch_bounds__(256, 1) layer2_kernel(
    const float* __restrict__ Whhf, const float* __restrict__ Whhb,
    const float* __restrict__ bhhf, const float* __restrict__ bhhb,
    float* __restrict__ ctx) {
    extern __shared__ __align__(16) float sm[];
    float* Wsh  = sm;                  // 48*1024
    float* hs   = sm + 48 * 1024;      // 1024
    float* gsum = hs + 1024;           // 48
    float* bsl  = gsum + 48;           // 48
    int tid = threadIdx.x, warp = tid >> 5, lane = tid & 31;
    int cta = blockIdx.x;
    int dir = cta >> 6;
    int j0 = (cta & 63) << 4;
    const float* Whh = dir ? Whhb : Whhf;
    const float* bhh = dir ? bhhb : bhhf;
    const float* GI  = dir ? g_gib : g_gif;

    // stage this CTA's 48 weight rows: local row l -> global row (l/16)*H2 + j0 + (l%16)
    for (int idx = tid; idx < 48 * 1024; idx += 256) {
        int l = idx >> 10, k = idx & 1023;
        int gr = (l >> 4) * H2 + j0 + (l & 15);
        Wsh[idx] = Whh[(size_t)gr * H2 + k];
    }
    if (tid < 48) bsl[tid] = bhh[(tid >> 4) * H2 + j0 + (tid & 15)];
    __syncthreads();

    for (int t = 0; t < STEPS; t++) {
        // load current h (L2-coherent) into smem
        const float* hrd = g_h2[dir][t & 1];
        float4 hv4 = __ldcg((const float4*)(hrd + tid * 4));
        ((float4*)hs)[tid] = hv4;
        __syncthreads();

        float4 hv[8];
#pragma unroll
        for (int k = 0; k < 8; k++) hv[k] = ((float4*)hs)[lane + 32 * k];

#pragma unroll
        for (int rr = 0; rr < 6; rr++) {
            int l = warp * 6 + rr;
            const float4* wr = (const float4*)(Wsh + l * 1024);
            float s = 0.f;
#pragma unroll
            for (int k = 0; k < 8; k++) {
                float4 wv = wr[lane + 32 * k];
                s += wv.x * hv[k].x + wv.y * hv[k].y + wv.z * hv[k].z + wv.w * hv[k].w;
            }
#pragma unroll
            for (int off = 16; off; off >>= 1) s += __shfl_xor_sync(0xffffffffu, s, off);
            if (lane == 0) gsum[l] = s;
        }
        __syncthreads();

        if (tid < 16) {
            int j = j0 + tid;
            int wd = dir ? (STEPS - 1 - t) : t;
            const float* gi = GI + (size_t)wd * G2;
            float hr = gsum[tid] + bsl[tid];
            float hz = gsum[16 + tid] + bsl[16 + tid];
            float hn = gsum[32 + tid] + bsl[32 + tid];
            float r = 1.f / (1.f + expf(-(gi[j] + hr)));
            float z = 1.f / (1.f + expf(-(gi[H2 + j] + hz)));
            float n = tanhf(gi[2 * H2 + j] + r * hn);
            float hnew = (1.f - z) * n + z * hs[j];
            ctx[(size_t)wd * (2 * H2) + dir * H2 + j] = hnew;
            __stcg(&g_h2[dir][(t + 1) & 1][j], hnew);
        }
        __syncthreads();

        // global barrier across 128 co-resident CTAs (monotonic counter,
        // nanosleep backoff to keep the L2 line cool)
        if (tid == 0) {
            __threadfence();
            atomicAdd(&g_bar, 1u);
            unsigned target = (unsigned)NCTA2 * (unsigned)(t + 1);
            while (__ldcg(&g_bar) < target) { __nanosleep(64); }
            __threadfence();
        }
        __syncthreads();
    }
}

extern "C" void kernel_launch(void* const* d_in, const int* in_sizes, int n_in,
                              void* d_out, int out_size) {
    const int*   x     = (const int*)d_in[0];
    const float* emb   = (const float*)d_in[1];
    const float* Wih1  = (const float*)d_in[2];
    const float* Whh1  = (const float*)d_in[3];
    const float* bih1  = (const float*)d_in[4];
    const float* bhh1  = (const float*)d_in[5];
    const float* Wih2f = (const float*)d_in[6];
    const float* Whh2f = (const float*)d_in[7];
    const float* bih2f = (const float*)d_in[8];
    const float* bhh2f = (const float*)d_in[9];
    const float* Wih2b = (const float*)d_in[10];
    const float* Whh2b = (const float*)d_in[11];
    const float* bih2b = (const float*)d_in[12];
    const float* bhh2b = (const float*)d_in[13];
    float* out = (float*)d_out;                 // [0, Wn*H1): word_emb
    float* ctx = out + (size_t)Wn * H1;         // [Wn*H1, +Wn*2*H2): ctx

    float *p_h1, *p_gh, *p_gif, *p_gib;
    cudaGetSymbolAddress((void**)&p_h1,  g_h1);
    cudaGetSymbolAddress((void**)&p_gh,  g_gh);
    cudaGetSymbolAddress((void**)&p_gif, g_gif);
    cudaGetSymbolAddress((void**)&p_gib, g_gib);

    init_kernel<<<8192, 256>>>();
    table_kernel<<<dim3(G1 / 64, Vn), 256>>>(emb, Wih1, bih1);

    dim3 gg(G1 / 128, Wn / 128);   // (24, 16)
    for (int t = 0; t < Cn; t++) {
        sgemm_nt<<<gg, 256>>>(p_h1, Whh1, p_gh, bhh1, Wn, G1, H1);
        gru1_kernel<<<8192, 256>>>(x, out, t);
    }

    sgemm_nt<<<gg, 256>>>(p_h1, Wih2f, p_gif, bih2f, Wn, G2, H1);
    sgemm_nt<<<gg, 256>>>(p_h1, Wih2b, p_gib, bih2b, Wn, G2, H1);

    int smem = (48 * 1024 + 1024 + 48 + 48) * (int)sizeof(float);
    cudaFuncSetAttribute(layer2_kernel, cudaFuncAttributeMaxDynamicSharedMemorySize, smem);
    layer2_kernel<<<NCTA2, 256, smem>>>(Whh2f, Whh2b, bhh2f, bhh2b, ctx);
}

// round 7
// speedup vs baseline: 1.8367x; 1.8367x over previous
#include <cuda_runtime.h>
#include <cuda_bf16.h>
#include <math.h>
#include <stdint.h>

#define Wn 2048
#define Cn 24
#define Vn 101
#define En 512
#define H1 1024
#define H2 1024
#define G1 3072
#define G2 3072
#define Kd 1024
#define KP 3072          // concatenated split-K: [hi | lo-pair | hi-pair]
#define NCTA2 128
#define STEPS 2048

// ---- scratch (__device__ globals; no allocations allowed) ----
__device__ float g_table[Vn * G1];
__device__ float g_h1[Wn * H1];
__device__ float g_gh[Wn * G1];
__device__ float g_gif[Wn * G2];
__device__ float g_gib[Wn * G2];
__device__ float g_h2[2][2][H2];
__device__ unsigned g_bar;
// bf16 concatenated-split operands
__device__ __nv_bfloat16 g_Ap[Wn * KP];        // [Ah | Ah | Al]
__device__ __nv_bfloat16 g_Wp1[G1 * KP];       // [Wh | Wl | Wh]
__device__ __nv_bfloat16 g_Wp2f[G2 * KP];
__device__ __nv_bfloat16 g_Wp2b[G2 * KP];

// =================== PTX helpers (base sm_103 target only) ===================
__device__ __forceinline__ uint32_t smem_u32(const void* p) {
    uint32_t a;
    asm("{ .reg .u64 t; cvta.to.shared.u64 t, %1; cvt.u32.u64 %0, t; }" : "=r"(a) : "l"(p));
    return a;
}
__device__ __forceinline__ void cpasync16(uint32_t dst, const void* src) {
    asm volatile("cp.async.cg.shared.global [%0], [%1], 16;" :: "r"(dst), "l"(src));
}
#define CP_COMMIT() asm volatile("cp.async.commit_group;" ::: "memory")
#define CP_WAIT1()  asm volatile("cp.async.wait_group 1;" ::: "memory")

__device__ __forceinline__ void ldm4(uint32_t* r, uint32_t addr) {
    asm volatile("ldmatrix.sync.aligned.m8n8.x4.shared.b16 {%0,%1,%2,%3}, [%4];"
        : "=r"(r[0]), "=r"(r[1]), "=r"(r[2]), "=r"(r[3]) : "r"(addr));
}
__device__ __forceinline__ void mma16816(float* d, const uint32_t* a, const uint32_t* b) {
    asm volatile("mma.sync.aligned.m16n8k16.row.col.f32.bf16.bf16.f32 "
        "{%0,%1,%2,%3}, {%4,%5,%6,%7}, {%8,%9}, {%0,%1,%2,%3};"
        : "+f"(d[0]), "+f"(d[1]), "+f"(d[2]), "+f"(d[3])
        : "r"(a[0]), "r"(a[1]), "r"(a[2]), "r"(a[3]), "r"(b[0]), "r"(b[1]));
}

// =================== bf16 HMMA GEMM: C[m][n] = A'[m]·B'[n] + bias[n] ===================
// M=2048, N=3072, K'=3072. 128x128 CTA tile, 8 warps x (64x32), k-step 32,
// 3-stage cp.async pipeline. Row pad 80B -> conflict-free ldmatrix.
#define STG 20480          // per-stage bytes: As 128*80 + Bs 128*80
#define NKIT (KP / 32)     // 96

__global__ void __launch_bounds__(256, 2) gemm_mma(
    const __nv_bfloat16* __restrict__ Ap, const __nv_bfloat16* __restrict__ Bp,
    float* __restrict__ C, const float* __restrict__ bias, int N) {
    extern __shared__ __align__(16) char smem[];
    const uint32_t sb = smem_u32(smem);
    const int tid = threadIdx.x, lane = tid & 31, warp = tid >> 5;
    const int wm = warp & 1, wn = warp >> 1;
    const int bm = blockIdx.y * 128, bn = blockIdx.x * 128;

    // cp.async mapping: thread handles rows r1 and r1+64, 16B chunk cc1
    const int r1 = tid >> 2, cc1 = tid & 3;
    const uint32_t dA1 = r1 * 80 + cc1 * 16, dA2 = dA1 + 64 * 80;
    const __nv_bfloat16* pa1 = Ap + (size_t)(bm + r1) * KP + cc1 * 8;
    const __nv_bfloat16* pa2 = pa1 + (size_t)64 * KP;
    const __nv_bfloat16* pb1 = Bp + (size_t)(bn + r1) * KP + cc1 * 8;
    const __nv_bfloat16* pb2 = pb1 + (size_t)64 * KP;

    // ldmatrix per-lane offsets (bytes)
    const uint32_t aPre = (uint32_t)(wm * 64 + ((lane >> 3) & 1) * 8 + (lane & 7)) * 80
                        + (uint32_t)(lane >> 4) * 16;
    const uint32_t bPre = (uint32_t)(wn * 32 + (lane >> 4) * 8 + (lane & 7)) * 80
                        + (uint32_t)((lane >> 3) & 1) * 16;

    float acc[4][4][4];
#pragma unroll
    for (int i = 0; i < 4; i++)
#pragma unroll
        for (int j = 0; j < 4; j++)
#pragma unroll
            for (int q = 0; q < 4; q++) acc[i][j][q] = 0.f;

#define ISSUE(s, k0) do { \
    uint32_t as_ = sb + (s) * STG, bs_ = as_ + 10240; \
    cpasync16(as_ + dA1, pa1 + (k0)); cpasync16(as_ + dA2, pa2 + (k0)); \
    cpasync16(bs_ + dA1, pb1 + (k0)); cpasync16(bs_ + dA2, pb2 + (k0)); \
} while (0)

    ISSUE(0, 0); CP_COMMIT();
    ISSUE(1, 32); CP_COMMIT();

    for (int it = 0; it < NKIT; it++) {
        CP_WAIT1();
        __syncthreads();
        if (it + 2 < NKIT) ISSUE((it + 2) % 3, (it + 2) * 32);
        CP_COMMIT();

        const uint32_t abase = sb + (it % 3) * STG;
        const uint32_t bbase = abase + 10240;
#pragma unroll
        for (int ks = 0; ks < 2; ks++) {
            uint32_t a[4][4], bb[2][4];
#pragma unroll
            for (int ma = 0; ma < 4; ma++) ldm4(a[ma], abase + aPre + ma * 1280 + ks * 32);
#pragma unroll
            for (int nb = 0; nb < 2; nb++) ldm4(bb[nb], bbase + bPre + nb * 1280 + ks * 32);
#pragma unroll
            for (int ma = 0; ma < 4; ma++)
#pragma unroll
                for (int na = 0; na < 4; na++)
                    mma16816(acc[ma][na], a[ma], &bb[na >> 1][(na & 1) * 2]);
        }
    }
#undef ISSUE

    const int g = lane >> 2, t = lane & 3;
#pragma unroll
    for (int ma = 0; ma < 4; ma++) {
        int m0 = bm + wm * 64 + ma * 16 + g;
#pragma unroll
        for (int na = 0; na < 4; na++) {
            int col = bn + wn * 32 + na * 8 + t * 2;
            float b0 = bias[col], b1 = bias[col + 1];
            *(float2*)(C + (size_t)m0 * N + col) =
                make_float2(acc[ma][na][0] + b0, acc[ma][na][1] + b1);
            *(float2*)(C + (size_t)(m0 + 8) * N + col) =
                make_float2(acc[ma][na][2] + b0, acc[ma][na][3] + b1);
        }
    }
}

// =================== init / conversions ===================
__global__ void init_kernel() {
    int i = blockIdx.x * 256 + threadIdx.x;           // 6.3M threads
    if (i < Wn * KP) g_Ap[i] = __nv_bfloat16(0.f);
    if (i < Wn * H1) g_h1[i] = 0.f;
    if (i < 4 * H2) ((float*)g_h2)[i] = 0.f;
    if (i == 0) g_bar = 0u;
}

// W (G x 1024) fp32 -> W' (G x 3072) bf16 = [hi | lo | hi]
__global__ void convsplit_kernel(const float* __restrict__ w,
                                 __nv_bfloat16* __restrict__ wp) {
    int i = blockIdx.x * 256 + threadIdx.x;
    if (i >= G1 * Kd) return;
    int r = i >> 10, k = i & 1023;
    float v = w[i];
    __nv_bfloat16 h = __float2bfloat16(v);
    __nv_bfloat16 l = __float2bfloat16(v - __bfloat162float(h));
    __nv_bfloat16* row = wp + (size_t)r * KP;
    row[k] = h; row[Kd + k] = l; row[2 * Kd + k] = h;
}

// ---- gi lookup ----
__global__ void table_kernel(const float* __restrict__ emb,
                             const float* __restrict__ Wih1,
                             const float* __restrict__ bih1) {
    __shared__ __align__(16) float e[En];
    int v = blockIdx.y;
    int tid = threadIdx.x, warp = tid >> 5, lane = tid & 31;
    for (int i = tid; i < En; i += 256) e[i] = emb[v * En + i];
    __syncthreads();
    int rbase = blockIdx.x * 64 + warp * 8;
    for (int rr = 0; rr < 8; rr++) {
        int row = rbase + rr;
        const float4* wp = (const float4*)(Wih1 + (size_t)row * En);
        const float4* ep = (const float4*)e;
        float s = 0.f;
#pragma unroll
        for (int k = 0; k < 4; k++) {
            float4 wv = wp[lane + 32 * k];
            float4 ev = ep[lane + 32 * k];
            s += wv.x * ev.x + wv.y * ev.y + wv.z * ev.z + wv.w * ev.w;
        }
        for (int off = 16; off; off >>= 1) s += __shfl_xor_sync(0xffffffffu, s, off);
        if (lane == 0) g_table[v * G1 + row] = s + bih1[row];
    }
}

// ---- layer-1 GRU pointwise (+ emit A' = [hi | hi | lo]) ----
__global__ void gru1_kernel(const int* __restrict__ x, float* __restrict__ out, int t) {
    int idx = blockIdx.x * 256 + threadIdx.x;
    int w = idx >> 10, j = idx & 1023;
    int ch = x[w * Cn + t];
    const float* tb = g_table + ch * G1;
    const float* gh = g_gh + (size_t)w * G1;
    float r = 1.f / (1.f + expf(-(tb[j] + gh[j])));
    float z = 1.f / (1.f + expf(-(tb[H1 + j] + gh[H1 + j])));
    float n = tanhf(tb[2 * H1 + j] + r * gh[2 * H1 + j]);
    float hp = g_h1[idx];
    float hn = (1.f - z) * n + z * hp;
    g_h1[idx] = hn;
    __nv_bfloat16 hh = __float2bfloat16(hn);
    __nv_bfloat16 hl = __float2bfloat16(hn - __bfloat162float(hh));
    __nv_bfloat16* arow = g_Ap + (size_t)w * KP;
    arow[j] = hh; arow[Kd + j] = hh; arow[2 * Kd + j] = hl;
    if (t == Cn - 1) out[idx] = hn;
}

// ---- layer-2 persistent bidirectional GRU (unchanged; passed R5) ----
__global__ void __launch_bounds__(256, 1) layer2_kernel(
    const float* __restrict__ Whhf, const float* __restrict__ Whhb,
    const float* __restrict__ bhhf, const float* __restrict__ bhhb,
    float* __restrict__ ctx) {
    extern __shared__ __align__(16) float sm[];
    float* Wsh  = sm;
    float* hs   = sm + 48 * 1024;
    float* gsum = hs + 1024;
    float* bsl  = gsum + 48;
    int tid = threadIdx.x, warp = tid >> 5, lane = tid & 31;
    int cta = blockIdx.x;
    int dir = cta >> 6;
    int j0 = (cta & 63) << 4;
    const float* Whh = dir ? Whhb : Whhf;
    const float* bhh = dir ? bhhb : bhhf;
    const float* GI  = dir ? g_gib : g_gif;

    for (int idx = tid; idx < 48 * 1024; idx += 256) {
        int l = idx >> 10, k = idx & 1023;
        int gr = (l >> 4) * H2 + j0 + (l & 15);
        Wsh[idx] = Whh[(size_t)gr * H2 + k];
    }
    if (tid < 48) bsl[tid] = bhh[(tid >> 4) * H2 + j0 + (tid & 15)];
    __syncthreads();

    for (int t = 0; t < STEPS; t++) {
        const float* hrd = g_h2[dir][t & 1];
        float4 hv4 = __ldcg((const float4*)(hrd + tid * 4));
        ((float4*)hs)[tid] = hv4;
        __syncthreads();

        float4 hv[8];
#pragma unroll
        for (int k = 0; k < 8; k++) hv[k] = ((float4*)hs)[lane + 32 * k];

#pragma unroll
        for (int rr = 0; rr < 6; rr++) {
            int l = warp * 6 + rr;
            const float4* wr = (const float4*)(Wsh + l * 1024);
            float s = 0.f;
#pragma unroll
            for (int k = 0; k < 8; k++) {
                float4 wv = wr[lane + 32 * k];
                s += wv.x * hv[k].x + wv.y * hv[k].y + wv.z * hv[k].z + wv.w * hv[k].w;
            }
#pragma unroll
            for (int off = 16; off; off >>= 1) s += __shfl_xor_sync(0xffffffffu, s, off);
            if (lane == 0) gsum[l] = s;
        }
        __syncthreads();

        if (tid < 16) {
            int j = j0 + tid;
            int wd = dir ? (STEPS - 1 - t) : t;
            const float* gi = GI + (size_t)wd * G2;
            float hr = gsum[tid] + bsl[tid];
            float hz = gsum[16 + tid] + bsl[16 + tid];
            float hn = gsum[32 + tid] + bsl[32 + tid];
            float r = 1.f / (1.f + expf(-(gi[j] + hr)));
            float z = 1.f / (1.f + expf(-(gi[H2 + j] + hz)));
            float n = tanhf(gi[2 * H2 + j] + r * hn);
            float hnew = (1.f - z) * n + z * hs[j];
            ctx[(size_t)wd * (2 * H2) + dir * H2 + j] = hnew;
            __stcg(&g_h2[dir][(t + 1) & 1][j], hnew);
        }
        __syncthreads();

        if (tid == 0) {
            __threadfence();
            atomicAdd(&g_bar, 1u);
            unsigned target = (unsigned)NCTA2 * (unsigned)(t + 1);
            while (__ldcg(&g_bar) < target) { __nanosleep(64); }
            __threadfence();
        }
        __syncthreads();
    }
}

extern "C" void kernel_launch(void* const* d_in, const int* in_sizes, int n_in,
                              void* d_out, int out_size) {
    const int*   x     = (const int*)d_in[0];
    const float* emb   = (const float*)d_in[1];
    const float* Wih1  = (const float*)d_in[2];
    const float* Whh1  = (const float*)d_in[3];
    const float* bih1  = (const float*)d_in[4];
    const float* bhh1  = (const float*)d_in[5];
    const float* Wih2f = (const float*)d_in[6];
    const float* Whh2f = (const float*)d_in[7];
    const float* bih2f = (const float*)d_in[8];
    const float* bhh2f = (const float*)d_in[9];
    const float* Wih2b = (const float*)d_in[10];
    const float* Whh2b = (const float*)d_in[11];
    const float* bih2b = (const float*)d_in[12];
    const float* bhh2b = (const float*)d_in[13];
    float* out = (float*)d_out;                 // word_emb (2048x1024)
    float* ctx = out + (size_t)Wn * H1;         // ctx (2048x2048)

    float *p_gh, *p_gif, *p_gib;
    cudaGetSymbolAddress((void**)&p_gh,  g_gh);
    cudaGetSymbolAddress((void**)&p_gif, g_gif);
    cudaGetSymbolAddress((void**)&p_gib, g_gib);
    __nv_bfloat16 *pAp, *pW1, *pW2f, *pW2b;
    cudaGetSymbolAddress((void**)&pAp,  g_Ap);
    cudaGetSymbolAddress((void**)&pW1,  g_Wp1);
    cudaGetSymbolAddress((void**)&pW2f, g_Wp2f);
    cudaGetSymbolAddress((void**)&pW2b, g_Wp2b);

    init_kernel<<<(Wn * KP + 255) / 256, 256>>>();
    table_kernel<<<dim3(G1 / 64, Vn), 256>>>(emb, Wih1, bih1);
    convsplit_kernel<<<(G1 * Kd + 255) / 256, 256>>>(Whh1,  pW1);
    convsplit_kernel<<<(G2 * Kd + 255) / 256, 256>>>(Wih2f, pW2f);
    convsplit_kernel<<<(G2 * Kd + 255) / 256, 256>>>(Wih2b, pW2b);

    const int gsmem = 3 * STG;   // 61,440 B
    cudaFuncSetAttribute(gemm_mma, cudaFuncAttributeMaxDynamicSharedMemorySize, gsmem);
    dim3 gg(G1 / 128, Wn / 128);            // (24, 16)

    for (int t = 0; t < Cn; t++) {
        gemm_mma<<<gg, 256, gsmem>>>(pAp, pW1, p_gh, bhh1, G1);
        gru1_kernel<<<8192, 256>>>(x, out, t);
    }

    gemm_mma<<<gg, 256, gsmem>>>(pAp, pW2f, p_gif, bih2f, G2);
    gemm_mma<<<gg, 256, gsmem>>>(pAp, pW2b, p_gib, bih2b, G2);

    int smem2 = (48 * 1024 + 1024 + 48 + 48) * (int)sizeof(float);
    cudaFuncSetAttribute(layer2_kernel, cudaFuncAttributeMaxDynamicSharedMemorySize, smem2);
    layer2_kernel<<<NCTA2, 256, smem2>>>(Whh2f, Whh2b, bhh2f, bhh2b, ctx);
}

// round 8
// speedup vs baseline: 2.3299x; 1.2685x over previous
#include <cuda_runtime.h>
#include <cuda_bf16.h>
#include <math.h>
#include <stdint.h>

#define Wn 2048
#define Cn 24
#define Vn 101
#define En 512
#define H1 1024
#define H2 1024
#define G1 3072
#define G2 3072
#define Kd 1024
#define KP 3072          // concatenated split-K: [hi | hi | lo] x [hi | lo | hi]
#define NCTA2 128
#define STEPS 2048

// ---- scratch (__device__ globals; no allocations allowed) ----
__device__ float g_table[Vn * G1];
__device__ float g_h1[Wn * H1];
__device__ float g_gh[Wn * G1];
__device__ float g_gif[Wn * G2];
__device__ float g_gib[Wn * G2];
__device__ float g_h2[2][2][H2];      // [dir][parity][dim]
__device__ unsigned g_bar2[2];        // per-direction barrier counters
// bf16 concatenated-split operands
__device__ __nv_bfloat16 g_Ap[Wn * KP];        // [Ah | Ah | Al]
__device__ __nv_bfloat16 g_Wp1[G1 * KP];       // [Wh | Wl | Wh]
__device__ __nv_bfloat16 g_Wp2f[G2 * KP];
__device__ __nv_bfloat16 g_Wp2b[G2 * KP];

// =================== PTX helpers (base sm_103 target only) ===================
__device__ __forceinline__ uint32_t smem_u32(const void* p) {
    uint32_t a;
    asm("{ .reg .u64 t; cvta.to.shared.u64 t, %1; cvt.u32.u64 %0, t; }" : "=r"(a) : "l"(p));
    return a;
}
__device__ __forceinline__ void cpasync16(uint32_t dst, const void* src) {
    asm volatile("cp.async.cg.shared.global [%0], [%1], 16;" :: "r"(dst), "l"(src));
}
#define CP_COMMIT() asm volatile("cp.async.commit_group;" ::: "memory")
#define CP_WAIT1()  asm volatile("cp.async.wait_group 1;" ::: "memory")

__device__ __forceinline__ void ldm4(uint32_t* r, uint32_t addr) {
    asm volatile("ldmatrix.sync.aligned.m8n8.x4.shared.b16 {%0,%1,%2,%3}, [%4];"
        : "=r"(r[0]), "=r"(r[1]), "=r"(r[2]), "=r"(r[3]) : "r"(addr));
}
__device__ __forceinline__ void mma16816(float* d, const uint32_t* a, const uint32_t* b) {
    asm volatile("mma.sync.aligned.m16n8k16.row.col.f32.bf16.bf16.f32 "
        "{%0,%1,%2,%3}, {%4,%5,%6,%7}, {%8,%9}, {%0,%1,%2,%3};"
        : "+f"(d[0]), "+f"(d[1]), "+f"(d[2]), "+f"(d[3])
        : "r"(a[0]), "r"(a[1]), "r"(a[2]), "r"(a[3]), "r"(b[0]), "r"(b[1]));
}
__device__ __forceinline__ void bar_arrive_release(unsigned* p) {
    asm volatile("red.release.gpu.global.add.u32 [%0], 1;" :: "l"(p) : "memory");
}
__device__ __forceinline__ unsigned ld_acquire(const unsigned* p) {
    unsigned v;
    asm volatile("ld.acquire.gpu.global.u32 %0, [%1];" : "=r"(v) : "l"(p) : "memory");
    return v;
}

// =================== bf16 HMMA GEMM (unchanged; passed R6) ===================
#define STG 20480
#define NKIT (KP / 32)

__global__ void __launch_bounds__(256, 2) gemm_mma(
    const __nv_bfloat16* __restrict__ Ap, const __nv_bfloat16* __restrict__ Bp,
    float* __restrict__ C, const float* __restrict__ bias, int N) {
    extern __shared__ __align__(16) char smem[];
    const uint32_t sb = smem_u32(smem);
    const int tid = threadIdx.x, lane = tid & 31, warp = tid >> 5;
    const int wm = warp & 1, wn = warp >> 1;
    const int bm = blockIdx.y * 128, bn = blockIdx.x * 128;

    const int r1 = tid >> 2, cc1 = tid & 3;
    const uint32_t dA1 = r1 * 80 + cc1 * 16, dA2 = dA1 + 64 * 80;
    const __nv_bfloat16* pa1 = Ap + (size_t)(bm + r1) * KP + cc1 * 8;
    const __nv_bfloat16* pa2 = pa1 + (size_t)64 * KP;
    const __nv_bfloat16* pb1 = Bp + (size_t)(bn + r1) * KP + cc1 * 8;
    const __nv_bfloat16* pb2 = pb1 + (size_t)64 * KP;

    const uint32_t aPre = (uint32_t)(wm * 64 + ((lane >> 3) & 1) * 8 + (lane & 7)) * 80
                        + (uint32_t)(lane >> 4) * 16;
    const uint32_t bPre = (uint32_t)(wn * 32 + (lane >> 4) * 8 + (lane & 7)) * 80
                        + (uint32_t)((lane >> 3) & 1) * 16;

    float acc[4][4][4];
#pragma unroll
    for (int i = 0; i < 4; i++)
#pragma unroll
        for (int j = 0; j < 4; j++)
#pragma unroll
            for (int q = 0; q < 4; q++) acc[i][j][q] = 0.f;

#define ISSUE(s, k0) do { \
    uint32_t as_ = sb + (s) * STG, bs_ = as_ + 10240; \
    cpasync16(as_ + dA1, pa1 + (k0)); cpasync16(as_ + dA2, pa2 + (k0)); \
    cpasync16(bs_ + dA1, pb1 + (k0)); cpasync16(bs_ + dA2, pb2 + (k0)); \
} while (0)

    ISSUE(0, 0); CP_COMMIT();
    ISSUE(1, 32); CP_COMMIT();

    for (int it = 0; it < NKIT; it++) {
        CP_WAIT1();
        __syncthreads();
        if (it + 2 < NKIT) ISSUE((it + 2) % 3, (it + 2) * 32);
        CP_COMMIT();

        const uint32_t abase = sb + (it % 3) * STG;
        const uint32_t bbase = abase + 10240;
#pragma unroll
        for (int ks = 0; ks < 2; ks++) {
            uint32_t a[4][4], bb[2][4];
#pragma unroll
            for (int ma = 0; ma < 4; ma++) ldm4(a[ma], abase + aPre + ma * 1280 + ks * 32);
#pragma unroll
            for (int nb = 0; nb < 2; nb++) ldm4(bb[nb], bbase + bPre + nb * 1280 + ks * 32);
#pragma unroll
            for (int ma = 0; ma < 4; ma++)
#pragma unroll
                for (int na = 0; na < 4; na++)
                    mma16816(acc[ma][na], a[ma], &bb[na >> 1][(na & 1) * 2]);
        }
    }
#undef ISSUE

    const int g = lane >> 2, t = lane & 3;
#pragma unroll
    for (int ma = 0; ma < 4; ma++) {
        int m0 = bm + wm * 64 + ma * 16 + g;
#pragma unroll
        for (int na = 0; na < 4; na++) {
            int col = bn + wn * 32 + na * 8 + t * 2;
            float b0 = bias[col], b1 = bias[col + 1];
            *(float2*)(C + (size_t)m0 * N + col) =
                make_float2(acc[ma][na][0] + b0, acc[ma][na][1] + b1);
            *(float2*)(C + (size_t)(m0 + 8) * N + col) =
                make_float2(acc[ma][na][2] + b0, acc[ma][na][3] + b1);
        }
    }
}

// =================== init / conversions ===================
__global__ void init_kernel() {
    int i = blockIdx.x * 256 + threadIdx.x;
    if (i < Wn * H1) g_h1[i] = 0.f;
    if (i < 4 * H2) ((float*)g_h2)[i] = 0.f;
    if (i < 2) g_bar2[i] = 0u;
}

__global__ void convsplit_kernel(const float* __restrict__ w,
                                 __nv_bfloat16* __restrict__ wp) {
    int i = blockIdx.x * 256 + threadIdx.x;
    if (i >= G1 * Kd) return;
    int r = i >> 10, k = i & 1023;
    float v = w[i];
    __nv_bfloat16 h = __float2bfloat16(v);
    __nv_bfloat16 l = __float2bfloat16(v - __bfloat162float(h));
    __nv_bfloat16* row = wp + (size_t)r * KP;
    row[k] = h; row[Kd + k] = l; row[2 * Kd + k] = h;
}

__global__ void table_kernel(const float* __restrict__ emb,
                             const float* __restrict__ Wih1,
                             const float* __restrict__ bih1) {
    __shared__ __align__(16) float e[En];
    int v = blockIdx.y;
    int tid = threadIdx.x, warp = tid >> 5, lane = tid & 31;
    for (int i = tid; i < En; i += 256) e[i] = emb[v * En + i];
    __syncthreads();
    int rbase = blockIdx.x * 64 + warp * 8;
    for (int rr = 0; rr < 8; rr++) {
        int row = rbase + rr;
        const float4* wp = (const float4*)(Wih1 + (size_t)row * En);
        const float4* ep = (const float4*)e;
        float s = 0.f;
#pragma unroll
        for (int k = 0; k < 4; k++) {
            float4 wv = wp[lane + 32 * k];
            float4 ev = ep[lane + 32 * k];
            s += wv.x * ev.x + wv.y * ev.y + wv.z * ev.z + wv.w * ev.w;
        }
        for (int off = 16; off; off >>= 1) s += __shfl_xor_sync(0xffffffffu, s, off);
        if (lane == 0) g_table[v * G1 + row] = s + bih1[row];
    }
}

// ---- layer-1 GRU pointwise (+ emit A'); t==0 uses gh = bhh directly ----
__global__ void gru1_kernel(const int* __restrict__ x, float* __restrict__ out,
                            int t, const float* __restrict__ bhh) {
    int idx = blockIdx.x * 256 + threadIdx.x;
    int w = idx >> 10, j = idx & 1023;
    int ch = x[w * Cn + t];
    const float* tb = g_table + ch * G1;
    float ghr, ghz, ghn;
    if (t == 0) {
        ghr = bhh[j]; ghz = bhh[H1 + j]; ghn = bhh[2 * H1 + j];
    } else {
        const float* gh = g_gh + (size_t)w * G1;
        ghr = gh[j]; ghz = gh[H1 + j]; ghn = gh[2 * H1 + j];
    }
    float r = 1.f / (1.f + expf(-(tb[j] + ghr)));
    float z = 1.f / (1.f + expf(-(tb[H1 + j] + ghz)));
    float n = tanhf(tb[2 * H1 + j] + r * ghn);
    float hp = g_h1[idx];
    float hn = (1.f - z) * n + z * hp;
    g_h1[idx] = hn;
    __nv_bfloat16 hh = __float2bfloat16(hn);
    __nv_bfloat16 hl = __float2bfloat16(hn - __bfloat162float(hh));
    __nv_bfloat16* arow = g_Ap + (size_t)w * KP;
    arow[j] = hh; arow[Kd + j] = hh; arow[2 * Kd + j] = hl;
    if (t == Cn - 1) out[idx] = hn;
}

// ---- layer-2 persistent bi-GRU: register-resident weights ----
// 128 CTAs (64/dir), each owns 16 h-dims (48 gate rows). Thread (warp,lane)
// holds rows warp*6..+5, k-slice {c*128 + lane*4 ..+3 : c<8} -> 192 regs.
__global__ void __launch_bounds__(256, 1) layer2_kernel(
    const float* __restrict__ Whhf, const float* __restrict__ Whhb,
    const float* __restrict__ bhhf, const float* __restrict__ bhhb,
    float* __restrict__ ctx) {
    __shared__ __align__(16) float hs[1024];
    __shared__ float gsum[48];
    __shared__ float bsl[48];
    const int tid = threadIdx.x, warp = tid >> 5, lane = tid & 31;
    const int cta = blockIdx.x, dir = cta >> 6, j0 = (cta & 63) << 4;
    const float* Whh = dir ? Whhb : Whhf;
    const float* bhh = dir ? bhhb : bhhf;
    const float* GI  = dir ? g_gib : g_gif;
    unsigned* barp = &g_bar2[dir];

    // one-time: stage weights into registers
    float4 wreg[6][8];
#pragma unroll
    for (int rr = 0; rr < 6; rr++) {
        int l = warp * 6 + rr;
        int gr = (l >> 4) * H2 + j0 + (l & 15);
        const float4* wp = (const float4*)(Whh + (size_t)gr * H2);
#pragma unroll
        for (int c = 0; c < 8; c++) wreg[rr][c] = wp[c * 32 + lane];
    }
    if (tid < 48) bsl[tid] = bhh[(tid >> 4) * H2 + j0 + (tid & 15)];
    __syncthreads();

    for (int t = 0; t < STEPS; t++) {
        // stage current h (L2-coherent) into smem
        const float4* hrd = (const float4*)g_h2[dir][t & 1];
        ((float4*)hs)[tid] = __ldcg(hrd + tid);
        __syncthreads();

        float acc[6] = {0.f, 0.f, 0.f, 0.f, 0.f, 0.f};
#pragma unroll
        for (int c = 0; c < 8; c++) {
            float4 h4 = ((const float4*)hs)[c * 32 + lane];
#pragma unroll
            for (int rr = 0; rr < 6; rr++) {
                acc[rr] += wreg[rr][c].x * h4.x + wreg[rr][c].y * h4.y
                         + wreg[rr][c].z * h4.z + wreg[rr][c].w * h4.w;
            }
        }
#pragma unroll
        for (int rr = 0; rr < 6; rr++) {
            float s = acc[rr];
#pragma unroll
            for (int off = 16; off; off >>= 1) s += __shfl_xor_sync(0xffffffffu, s, off);
            if (lane == 0) gsum[warp * 6 + rr] = s;
        }
        __syncthreads();

        if (tid < 16) {
            int j = j0 + tid;
            int wd = dir ? (STEPS - 1 - t) : t;
            const float* gi = GI + (size_t)wd * G2;
            float hr = gsum[tid] + bsl[tid];
            float hz = gsum[16 + tid] + bsl[16 + tid];
            float hn = gsum[32 + tid] + bsl[32 + tid];
            float r = 1.f / (1.f + expf(-(gi[j] + hr)));
            float z = 1.f / (1.f + expf(-(gi[H2 + j] + hz)));
            float n = tanhf(gi[2 * H2 + j] + r * hn);
            float hnew = (1.f - z) * n + z * hs[j];
            ctx[(size_t)wd * (2 * H2) + dir * H2 + j] = hnew;
            __stcg(&g_h2[dir][(t + 1) & 1][j], hnew);
        }
        __syncthreads();

        // per-direction release/acquire barrier (64 arrivals)
        if (tid == 0) {
            bar_arrive_release(barp);
            unsigned target = 64u * (unsigned)(t + 1);
            while (ld_acquire(barp) < target) { __nanosleep(32); }
        }
        __syncthreads();
    }
}

extern "C" void kernel_launch(void* const* d_in, const int* in_sizes, int n_in,
                              void* d_out, int out_size) {
    const int*   x     = (const int*)d_in[0];
    const float* emb   = (const float*)d_in[1];
    const float* Wih1  = (const float*)d_in[2];
    const float* Whh1  = (const float*)d_in[3];
    const float* bih1  = (const float*)d_in[4];
    const float* bhh1  = (const float*)d_in[5];
    const float* Wih2f = (const float*)d_in[6];
    const float* Whh2f = (const float*)d_in[7];
    const float* bih2f = (const float*)d_in[8];
    const float* bhh2f = (const float*)d_in[9];
    const float* Wih2b = (const float*)d_in[10];
    const float* Whh2b = (const float*)d_in[11];
    const float* bih2b = (const float*)d_in[12];
    const float* bhh2b = (const float*)d_in[13];
    float* out = (float*)d_out;
    float* ctx = out + (size_t)Wn * H1;

    float *p_gh, *p_gif, *p_gib;
    cudaGetSymbolAddress((void**)&p_gh,  g_gh);
    cudaGetSymbolAddress((void**)&p_gif, g_gif);
    cudaGetSymbolAddress((void**)&p_gib, g_gib);
    __nv_bfloat16 *pAp, *pW1, *pW2f, *pW2b;
    cudaGetSymbolAddress((void**)&pAp,  g_Ap);
    cudaGetSymbolAddress((void**)&pW1,  g_Wp1);
    cudaGetSymbolAddress((void**)&pW2f, g_Wp2f);
    cudaGetSymbolAddress((void**)&pW2b, g_Wp2b);

    init_kernel<<<(Wn * H1 + 255) / 256, 256>>>();
    table_kernel<<<dim3(G1 / 64, Vn), 256>>>(emb, Wih1, bih1);
    convsplit_kernel<<<(G1 * Kd + 255) / 256, 256>>>(Whh1,  pW1);
    convsplit_kernel<<<(G2 * Kd + 255) / 256, 256>>>(Wih2f, pW2f);
    convsplit_kernel<<<(G2 * Kd + 255) / 256, 256>>>(Wih2b, pW2b);

    const int gsmem = 3 * STG;
    cudaFuncSetAttribute(gemm_mma, cudaFuncAttributeMaxDynamicSharedMemorySize, gsmem);
    dim3 gg(G1 / 128, Wn / 128);

    gru1_kernel<<<8192, 256>>>(x, out, 0, bhh1);          // h0 = 0 -> gh = bhh1
    for (int t = 1; t < Cn; t++) {
        gemm_mma<<<gg, 256, gsmem>>>(pAp, pW1, p_gh, bhh1, G1);
        gru1_kernel<<<8192, 256>>>(x, out, t, bhh1);
    }

    gemm_mma<<<gg, 256, gsmem>>>(pAp, pW2f, p_gif, bih2f, G2);
    gemm_mma<<<gg, 256, gsmem>>>(pAp, pW2b, p_gib, bih2b, G2);

    layer2_kernel<<<NCTA2, 256>>>(Whh2f, Whh2b, bhh2f, bhh2b, ctx);
}

// round 9
// speedup vs baseline: 3.1441x; 1.3495x over previous
#include <cuda_runtime.h>
#include <cuda_bf16.h>
#include <math.h>
#include <stdint.h>

#define Wn 2048
#define Cn 24
#define Vn 101
#define En 512
#define H1 1024
#define H2 1024
#define G1 3072
#define G2 3072
#define Kd 1024
#define KP 3072
#define NCTA2 128
#define STEPS 2048

// ---- scratch (__device__ globals; no allocations allowed) ----
__device__ float g_table[Vn * G1];
__device__ float g_h1[Wn * H1];
__device__ float g_gh[Wn * G1];
__device__ float g_gif[Wn * G2];
__device__ float g_gib[Wn * G2];
__device__ float g_h2[2][2][H2];      // [dir][parity][dim]
__device__ unsigned g_bar2[2];
__device__ __nv_bfloat16 g_Ap[Wn * KP];        // [Ah | Ah | Al]
__device__ __nv_bfloat16 g_Wp1[G1 * KP];       // [Wh | Wl | Wh]
__device__ __nv_bfloat16 g_Wp2f[G2 * KP];
__device__ __nv_bfloat16 g_Wp2b[G2 * KP];

// =================== PTX helpers ===================
__device__ __forceinline__ uint32_t smem_u32(const void* p) {
    uint32_t a;
    asm("{ .reg .u64 t; cvta.to.shared.u64 t, %1; cvt.u32.u64 %0, t; }" : "=r"(a) : "l"(p));
    return a;
}
__device__ __forceinline__ void cpasync16(uint32_t dst, const void* src) {
    asm volatile("cp.async.cg.shared.global [%0], [%1], 16;" :: "r"(dst), "l"(src));
}
#define CP_COMMIT() asm volatile("cp.async.commit_group;" ::: "memory")
#define CP_WAIT1()  asm volatile("cp.async.wait_group 1;" ::: "memory")

__device__ __forceinline__ void ldm4(uint32_t* r, uint32_t addr) {
    asm volatile("ldmatrix.sync.aligned.m8n8.x4.shared.b16 {%0,%1,%2,%3}, [%4];"
        : "=r"(r[0]), "=r"(r[1]), "=r"(r[2]), "=r"(r[3]) : "r"(addr));
}
__device__ __forceinline__ void mma16816(float* d, const uint32_t* a, const uint32_t* b) {
    asm volatile("mma.sync.aligned.m16n8k16.row.col.f32.bf16.bf16.f32 "
        "{%0,%1,%2,%3}, {%4,%5,%6,%7}, {%8,%9}, {%0,%1,%2,%3};"
        : "+f"(d[0]), "+f"(d[1]), "+f"(d[2]), "+f"(d[3])
        : "r"(a[0]), "r"(a[1]), "r"(a[2]), "r"(a[3]), "r"(b[0]), "r"(b[1]));
}
__device__ __forceinline__ void bar_arrive_release(unsigned* p) {
    asm volatile("red.release.gpu.global.add.u32 [%0], 1;" :: "l"(p) : "memory");
}
__device__ __forceinline__ unsigned ld_acquire(const unsigned* p) {
    unsigned v;
    asm volatile("ld.acquire.gpu.global.u32 %0, [%1];" : "=r"(v) : "l"(p) : "memory");
    return v;
}
__device__ __forceinline__ float tanh_fast(float x) {
    float y;
    asm("tanh.approx.f32 %0, %1;" : "=f"(y) : "f"(x));
    return y;
}
__device__ __forceinline__ float sigmoid_fast(float x) {
    return fmaf(tanh_fast(0.5f * x), 0.5f, 0.5f);
}

// =================== bf16 HMMA GEMM (unchanged; passed R6/R7) ===================
#define STG 20480
#define NKIT (KP / 32)

__global__ void __launch_bounds__(256, 2) gemm_mma(
    const __nv_bfloat16* __restrict__ Ap, const __nv_bfloat16* __restrict__ Bp,
    float* __restrict__ C, const float* __restrict__ bias, int N) {
    extern __shared__ __align__(16) char smem[];
    const uint32_t sb = smem_u32(smem);
    const int tid = threadIdx.x, lane = tid & 31, warp = tid >> 5;
    const int wm = warp & 1, wn = warp >> 1;
    const int bm = blockIdx.y * 128, bn = blockIdx.x * 128;

    const int r1 = tid >> 2, cc1 = tid & 3;
    const uint32_t dA1 = r1 * 80 + cc1 * 16, dA2 = dA1 + 64 * 80;
    const __nv_bfloat16* pa1 = Ap + (size_t)(bm + r1) * KP + cc1 * 8;
    const __nv_bfloat16* pa2 = pa1 + (size_t)64 * KP;
    const __nv_bfloat16* pb1 = Bp + (size_t)(bn + r1) * KP + cc1 * 8;
    const __nv_bfloat16* pb2 = pb1 + (size_t)64 * KP;

    const uint32_t aPre = (uint32_t)(wm * 64 + ((lane >> 3) & 1) * 8 + (lane & 7)) * 80
                        + (uint32_t)(lane >> 4) * 16;
    const uint32_t bPre = (uint32_t)(wn * 32 + (lane >> 4) * 8 + (lane & 7)) * 80
                        + (uint32_t)((lane >> 3) & 1) * 16;

    float acc[4][4][4];
#pragma unroll
    for (int i = 0; i < 4; i++)
#pragma unroll
        for (int j = 0; j < 4; j++)
#pragma unroll
            for (int q = 0; q < 4; q++) acc[i][j][q] = 0.f;

#define ISSUE(s, k0) do { \
    uint32_t as_ = sb + (s) * STG, bs_ = as_ + 10240; \
    cpasync16(as_ + dA1, pa1 + (k0)); cpasync16(as_ + dA2, pa2 + (k0)); \
    cpasync16(bs_ + dA1, pb1 + (k0)); cpasync16(bs_ + dA2, pb2 + (k0)); \
} while (0)

    ISSUE(0, 0); CP_COMMIT();
    ISSUE(1, 32); CP_COMMIT();

    for (int it = 0; it < NKIT; it++) {
        CP_WAIT1();
        __syncthreads();
        if (it + 2 < NKIT) ISSUE((it + 2) % 3, (it + 2) * 32);
        CP_COMMIT();

        const uint32_t abase = sb + (it % 3) * STG;
        const uint32_t bbase = abase + 10240;
#pragma unroll
        for (int ks = 0; ks < 2; ks++) {
            uint32_t a[4][4], bb[2][4];
#pragma unroll
            for (int ma = 0; ma < 4; ma++) ldm4(a[ma], abase + aPre + ma * 1280 + ks * 32);
#pragma unroll
            for (int nb = 0; nb < 2; nb++) ldm4(bb[nb], bbase + bPre + nb * 1280 + ks * 32);
#pragma unroll
            for (int ma = 0; ma < 4; ma++)
#pragma unroll
                for (int na = 0; na < 4; na++)
                    mma16816(acc[ma][na], a[ma], &bb[na >> 1][(na & 1) * 2]);
        }
    }
#undef ISSUE

    const int g = lane >> 2, t = lane & 3;
#pragma unroll
    for (int ma = 0; ma < 4; ma++) {
        int m0 = bm + wm * 64 + ma * 16 + g;
#pragma unroll
        for (int na = 0; na < 4; na++) {
            int col = bn + wn * 32 + na * 8 + t * 2;
            float b0 = bias[col], b1 = bias[col + 1];
            *(float2*)(C + (size_t)m0 * N + col) =
                make_float2(acc[ma][na][0] + b0, acc[ma][na][1] + b1);
            *(float2*)(C + (size_t)(m0 + 8) * N + col) =
                make_float2(acc[ma][na][2] + b0, acc[ma][na][3] + b1);
        }
    }
}

// =================== init / conversions ===================
__global__ void init_kernel() {
    int i = blockIdx.x * 256 + threadIdx.x;
    if (i < Wn * H1) g_h1[i] = 0.f;
    if (i < 4 * H2) ((float*)g_h2)[i] = 0.f;
    if (i < 2) g_bar2[i] = 0u;
}

__global__ void convsplit_kernel(const float* __restrict__ w,
                                 __nv_bfloat16* __restrict__ wp) {
    int i = blockIdx.x * 256 + threadIdx.x;
    if (i >= G1 * Kd) return;
    int r = i >> 10, k = i & 1023;
    float v = w[i];
    __nv_bfloat16 h = __float2bfloat16(v);
    __nv_bfloat16 l = __float2bfloat16(v - __bfloat162float(h));
    __nv_bfloat16* row = wp + (size_t)r * KP;
    row[k] = h; row[Kd + k] = l; row[2 * Kd + k] = h;
}

__global__ void table_kernel(const float* __restrict__ emb,
                             const float* __restrict__ Wih1,
                             const float* __restrict__ bih1) {
    __shared__ __align__(16) float e[En];
    int v = blockIdx.y;
    int tid = threadIdx.x, warp = tid >> 5, lane = tid & 31;
    for (int i = tid; i < En; i += 256) e[i] = emb[v * En + i];
    __syncthreads();
    int rbase = blockIdx.x * 64 + warp * 8;
    for (int rr = 0; rr < 8; rr++) {
        int row = rbase + rr;
        const float4* wp = (const float4*)(Wih1 + (size_t)row * En);
        const float4* ep = (const float4*)e;
        float s = 0.f;
#pragma unroll
        for (int k = 0; k < 4; k++) {
            float4 wv = wp[lane + 32 * k];
            float4 ev = ep[lane + 32 * k];
            s += wv.x * ev.x + wv.y * ev.y + wv.z * ev.z + wv.w * ev.w;
        }
        for (int off = 16; off; off >>= 1) s += __shfl_xor_sync(0xffffffffu, s, off);
        if (lane == 0) g_table[v * G1 + row] = s + bih1[row];
    }
}

// ---- layer-1 GRU pointwise (+ emit A'); t==0 uses gh = bhh ----
__global__ void gru1_kernel(const int* __restrict__ x, float* __restrict__ out,
                            int t, const float* __restrict__ bhh) {
    int idx = blockIdx.x * 256 + threadIdx.x;
    int w = idx >> 10, j = idx & 1023;
    int ch = x[w * Cn + t];
    const float* tb = g_table + ch * G1;
    float ghr, ghz, ghn;
    if (t == 0) {
        ghr = bhh[j]; ghz = bhh[H1 + j]; ghn = bhh[2 * H1 + j];
    } else {
        const float* gh = g_gh + (size_t)w * G1;
        ghr = gh[j]; ghz = gh[H1 + j]; ghn = gh[2 * H1 + j];
    }
    float r = 1.f / (1.f + expf(-(tb[j] + ghr)));
    float z = 1.f / (1.f + expf(-(tb[H1 + j] + ghz)));
    float n = tanhf(tb[2 * H1 + j] + r * ghn);
    float hp = g_h1[idx];
    float hn = (1.f - z) * n + z * hp;
    g_h1[idx] = hn;
    __nv_bfloat16 hh = __float2bfloat16(hn);
    __nv_bfloat16 hl = __float2bfloat16(hn - __bfloat162float(hh));
    __nv_bfloat16* arow = g_Ap + (size_t)w * KP;
    arow[j] = hh; arow[Kd + j] = hh; arow[2 * Kd + j] = hl;
    if (t == Cn - 1) out[idx] = hn;
}

// ---- layer-2 persistent bi-GRU: warp-local gates, reg weights, gi prefetch ----
// 128 CTAs (64/dir). Warp w owns h-dims {j0+2w, j0+2w+1} and ALL 3 gate rows
// for them (6 rows, 192 weight floats/thread). Gate math entirely on lane 0.
__global__ void __launch_bounds__(256, 1) layer2_kernel(
    const float* __restrict__ Whhf, const float* __restrict__ Whhb,
    const float* __restrict__ bhhf, const float* __restrict__ bhhb,
    float* __restrict__ ctx) {
    __shared__ __align__(16) float hs[1024];
    const int tid = threadIdx.x, warp = tid >> 5, lane = tid & 31;
    const int cta = blockIdx.x, dir = cta >> 6, j0 = (cta & 63) << 4;
    const float* Whh = dir ? Whhb : Whhf;
    const float* bhh = dir ? bhhb : bhhf;
    const float* GI  = dir ? g_gib : g_gif;
    unsigned* barp = &g_bar2[dir];
    const int d0 = j0 + 2 * warp;         // this warp's first h-dim

    // one-time: stage 6 weight rows into registers: row order [u][g]
    float4 wreg[6][8];
#pragma unroll
    for (int u = 0; u < 2; u++)
#pragma unroll
        for (int gg = 0; gg < 3; gg++) {
            const float4* wp = (const float4*)(Whh + (size_t)(gg * H2 + d0 + u) * H2);
#pragma unroll
            for (int c = 0; c < 8; c++) wreg[u * 3 + gg][c] = wp[c * 32 + lane];
        }
    float bg[6];
#pragma unroll
    for (int u = 0; u < 2; u++)
#pragma unroll
        for (int gg = 0; gg < 3; gg++) bg[u * 3 + gg] = bhh[gg * H2 + d0 + u];

    for (int t = 0; t < STEPS; t++) {
        const int wd = dir ? (STEPS - 1 - t) : t;
        const float* gi = GI + (size_t)wd * G2;

        // stage h; prefetch gi (independent of h) to hide L2 latency
        ((float4*)hs)[tid] = __ldcg(((const float4*)g_h2[dir][t & 1]) + tid);
        float giv[6];
        if (lane == 0) {
#pragma unroll
            for (int u = 0; u < 2; u++)
#pragma unroll
                for (int gg = 0; gg < 3; gg++) giv[u * 3 + gg] = gi[gg * H2 + d0 + u];
        }
        __syncthreads();

        float acc[6] = {0.f, 0.f, 0.f, 0.f, 0.f, 0.f};
#pragma unroll
        for (int c = 0; c < 8; c++) {
            float4 h4 = ((const float4*)hs)[c * 32 + lane];
#pragma unroll
            for (int rr = 0; rr < 6; rr++)
                acc[rr] += wreg[rr][c].x * h4.x + wreg[rr][c].y * h4.y
                         + wreg[rr][c].z * h4.z + wreg[rr][c].w * h4.w;
        }
#pragma unroll
        for (int off = 16; off; off >>= 1)
#pragma unroll
            for (int rr = 0; rr < 6; rr++)
                acc[rr] += __shfl_xor_sync(0xffffffffu, acc[rr], off);

        if (lane == 0) {
            float hnew[2];
#pragma unroll
            for (int u = 0; u < 2; u++) {
                float r = sigmoid_fast(giv[u * 3 + 0] + acc[u * 3 + 0] + bg[u * 3 + 0]);
                float z = sigmoid_fast(giv[u * 3 + 1] + acc[u * 3 + 1] + bg[u * 3 + 1]);
                float n = tanh_fast(giv[u * 3 + 2] + r * (acc[u * 3 + 2] + bg[u * 3 + 2]));
                hnew[u] = (1.f - z) * n + z * hs[d0 + u];
            }
            *(float2*)(ctx + (size_t)wd * (2 * H2) + dir * H2 + d0) = make_float2(hnew[0], hnew[1]);
            float2* hwr = (float2*)&g_h2[dir][(t + 1) & 1][d0];
            __stcg(hwr, make_float2(hnew[0], hnew[1]));
        }
        __syncthreads();                  // all warps' h-stores ordered before arrive

        if (tid == 0) {
            bar_arrive_release(barp);
            unsigned target = 64u * (unsigned)(t + 1);
            while (ld_acquire(barp) < target) { __nanosleep(16); }
        }
        __syncthreads();
    }
}

extern "C" void kernel_launch(void* const* d_in, const int* in_sizes, int n_in,
                              void* d_out, int out_size) {
    const int*   x     = (const int*)d_in[0];
    const float* emb   = (const float*)d_in[1];
    const float* Wih1  = (const float*)d_in[2];
    const float* Whh1  = (const float*)d_in[3];
    const float* bih1  = (const float*)d_in[4];
    const float* bhh1  = (const float*)d_in[5];
    const float* Wih2f = (const float*)d_in[6];
    const float* Whh2f = (const float*)d_in[7];
    const float* bih2f = (const float*)d_in[8];
    const float* bhh2f = (const float*)d_in[9];
    const float* Wih2b = (const float*)d_in[10];
    const float* Whh2b = (const float*)d_in[11];
    const float* bih2b = (const float*)d_in[12];
    const float* bhh2b = (const float*)d_in[13];
    float* out = (float*)d_out;
    float* ctx = out + (size_t)Wn * H1;

    float *p_gh, *p_gif, *p_gib;
    cudaGetSymbolAddress((void**)&p_gh,  g_gh);
    cudaGetSymbolAddress((void**)&p_gif, g_gif);
    cudaGetSymbolAddress((void**)&p_gib, g_gib);
    __nv_bfloat16 *pAp, *pW1, *pW2f, *pW2b;
    cudaGetSymbolAddress((void**)&pAp,  g_Ap);
    cudaGetSymbolAddress((void**)&pW1,  g_Wp1);
    cudaGetSymbolAddress((void**)&pW2f, g_Wp2f);
    cudaGetSymbolAddress((void**)&pW2b, g_Wp2b);

    const int gsmem = 3 * STG;
    cudaFuncSetAttribute(gemm_mma, cudaFuncAttributeMaxDynamicSharedMemorySize, gsmem);
    dim3 gg(G1 / 128, Wn / 128);

    // Launch order puts gemm_mma in the ncu capture window (launch idx ~4-6).
    init_kernel<<<(Wn * H1 + 255) / 256, 256>>>();                 // 0
    table_kernel<<<dim3(G1 / 64, Vn), 256>>>(emb, Wih1, bih1);     // 1
    gru1_kernel<<<8192, 256>>>(x, out, 0, bhh1);                   // 2
    convsplit_kernel<<<(G1 * Kd + 255) / 256, 256>>>(Whh1, pW1);   // 3
    for (int t = 1; t < Cn; t++) {
        gemm_mma<<<gg, 256, gsmem>>>(pAp, pW1, p_gh, bhh1, G1);    // 4, 6, 8, ...
        gru1_kernel<<<8192, 256>>>(x, out, t, bhh1);               // 5, 7, 9, ...
    }

    convsplit_kernel<<<(G2 * Kd + 255) / 256, 256>>>(Wih2f, pW2f);
    gemm_mma<<<gg, 256, gsmem>>>(pAp, pW2f, p_gif, bih2f, G2);
    convsplit_kernel<<<(G2 * Kd + 255) / 256, 256>>>(Wih2b, pW2b);
    gemm_mma<<<gg, 256, gsmem>>>(pAp, pW2b, p_gib, bih2b, G2);

    layer2_kernel<<<NCTA2, 256>>>(Whh2f, Whh2b, bhh2f, bhh2b, ctx);
}